// round 1
// baseline (speedup 1.0000x reference)
#include <cuda_runtime.h>
#include <cuda_bf16.h>

// PositionalEmbedding: out[l, :] = emb_table[token_ids[l], :] + PE(l, :)
// PE pairs p in [0,255): col 2p = sin(l / 10000^(2p/512)), col 2p+1 = cos(...).
// Cols 510, 511 get PE = 0 (reference only fills 255 pairs).

#define SEQ   131072
#define DEPTH 512

// Per-pair frequency w_p = 10000^(2p/512), correctly-rounded fp32 (computed in
// double by the setup kernel so it matches a correctly-rounded powf bit-for-bit).
__device__ float g_w[256];

__global__ void setup_freq_kernel() {
    int p = threadIdx.x;
    if (p < 255) {
        // y = 2p/512 is exact in double; exp in double then round to fp32.
        double y = (double)(2 * p) / 512.0;
        double w = exp(y * 9.210340371976184);  // ln(10000)
        g_w[p] = (float)w;
    } else if (p == 255) {
        g_w[p] = 1.0f;  // unused (guarded)
    }
}

// Accurate sin/cos of the fp32-rounded angle a = fl32(fi / w), mimicking
// jnp.sin/jnp.cos applied to the reference's fp32 angle.
//  - __fdiv_rn: IEEE round-to-nearest division (safe under --use_fast_math)
//  - two-word Cody-Waite reduction mod 2pi (k <= 20861 for a <= 131071)
//  - MUFU sin/cos on the reduced argument |r| <= pi + 0.01
__device__ __forceinline__ float2 pe_pair(float fi, float w) {
    float a = __fdiv_rn(fi, w);                       // exact fp32 angle (matches ref)
    float k = rintf(a * 0.15915494309189535f);        // nearest multiple of 2pi
    // 2pi = HI + MID; HI = fl32(2pi) = 6.283185482025146..., MID = 2pi - HI
    float r = fmaf(k, -6.283185307179586f, a);        // literal rounds to HI (0x40C90FDB)
    r = fmaf(k, 1.7484556e-07f, r);                   // subtract k*MID (MID < 0)
    float s, c;
    __sincosf(r, &s, &c);
    return make_float2(s, c);
}

__global__ void __launch_bounds__(256) emb_pe_kernel(
    const int*   __restrict__ tok,
    const float* __restrict__ tab,
    float*       __restrict__ out)
{
    const int tid = threadIdx.x;
    const int t   = tid & 127;                 // thread within row: float4 index
    const int row = (blockIdx.x << 1) | (tid >> 7);

    const int tk = __ldg(tok + row);

    // Gather one float4 of the embedding row (row start is 2048B-aligned).
    const float4 e = __ldg(reinterpret_cast<const float4*>(tab) + ((size_t)tk << 7) + t);

    // Frequencies for pairs p0 = 2t, p1 = 2t+1 — coalesced float2 load.
    const float2 w = __ldg(reinterpret_cast<const float2*>(g_w) + t);

    const float fi = (float)row;
    const int p0 = t << 1;

    float4 o;
    {   // pair p0 (always < 255 since t <= 127 -> p0 <= 254)
        float2 sc = pe_pair(fi, w.x);
        o.x = e.x + sc.x;
        o.y = e.y + sc.y;
    }
    if (p0 + 1 < 255) {  // pair p1; only t == 127 hits the zero-PE tail
        float2 sc = pe_pair(fi, w.y);
        o.z = e.z + sc.x;
        o.w = e.w + sc.y;
    } else {
        o.z = e.z;
        o.w = e.w;
    }

    // Streaming store (evict-first) so the 256MB output stream does not evict
    // the 103MB embedding table from L2.
    __stcs(reinterpret_cast<float4*>(out) + ((size_t)row << 7) + t, o);
}

extern "C" void kernel_launch(void* const* d_in, const int* in_sizes, int n_in,
                              void* d_out, int out_size) {
    const int*   tok = (const int*)d_in[0];     // token_ids, int32 [131072]
    const float* tab = (const float*)d_in[1];   // emb_table, fp32 [50257, 512]
    float*       out = (float*)d_out;           // fp32 [131072, 512]

    setup_freq_kernel<<<1, 256>>>();
    emb_pe_kernel<<<SEQ / 2, 256>>>(tok, tab, out);
}

// round 2
// speedup vs baseline: 1.3088x; 1.3088x over previous
#include <cuda_runtime.h>
#include <cuda_bf16.h>

// PositionalEmbedding: out[l, :] = emb_table[token_ids[l], :] + PE(l, :)
// PE pairs p in [0,255): col 2p = sin(l / 10000^(2p/512)), col 2p+1 = cos(...).
// Cols 510, 511 get PE = 0 (reference only fills 255 pairs).

#define SEQ   131072
#define DEPTH 512
#define ROWS_PER_GROUP 4   // rows handled by each 128-thread group

// Per-pair frequency w_p = 10000^(2p/512), correctly-rounded fp32 (computed in
// double so it matches the reference's fp32 frequency bit-for-bit).
__device__ float g_w[256];

__global__ void setup_freq_kernel() {
    int p = threadIdx.x;
    if (p < 255) {
        double y = (double)(2 * p) / 512.0;          // exact in double
        double w = exp(y * 9.210340371976184);       // ln(10000)
        g_w[p] = (float)w;
    } else if (p == 255) {
        g_w[p] = 1.0f;  // unused (guarded)
    }
}

// Accurate sin/cos of the fp32-rounded angle a = fl32(fi / w), mimicking
// jnp.sin/jnp.cos applied to the reference's fp32 angle.
//  - __fdiv_rn: IEEE round-to-nearest division (matches reference's angle bits)
//  - two-word Cody-Waite reduction mod 2pi (k <= 20861 for a <= 131071)
//  - MUFU sin/cos on the reduced argument |r| <= pi + 0.01
__device__ __forceinline__ float2 pe_pair(float fi, float w) {
    float a = __fdiv_rn(fi, w);
    float k = rintf(a * 0.15915494309189535f);
    // 2pi = HI + MID; HI = fl32(2pi), MID = 2pi - HI = -1.7484555e-7
    float r = fmaf(k, -6.283185307179586f, a);   // literal rounds to HI
    r = fmaf(k, 1.7484556e-07f, r);              // add back k*(HI - 2pi)
    float s, c;
    __sincosf(r, &s, &c);
    return make_float2(s, c);
}

__global__ void __launch_bounds__(256) emb_pe_kernel(
    const int*   __restrict__ tok,
    const float* __restrict__ tab,
    float*       __restrict__ out)
{
    const int tid  = threadIdx.x;
    const int t    = tid & 127;                  // float4 index within a row
    const int grp  = tid >> 7;                   // 0 or 1
    const int base = (blockIdx.x * 2 + grp) * ROWS_PER_GROUP;

    // ---- front-batched independent token loads (broadcast within group) ----
    int tk[ROWS_PER_GROUP];
#pragma unroll
    for (int r = 0; r < ROWS_PER_GROUP; r++)
        tk[r] = __ldg(tok + base + r);

    // ---- front-batched independent table gathers (2KB-aligned rows) ----
    float4 e[ROWS_PER_GROUP];
#pragma unroll
    for (int r = 0; r < ROWS_PER_GROUP; r++)
        e[r] = __ldg(reinterpret_cast<const float4*>(tab) + ((size_t)tk[r] << 7) + t);

    // frequencies for pairs p0 = 2t, p1 = 2t+1 — coalesced float2 load
    const float2 w    = __ldg(reinterpret_cast<const float2*>(g_w) + t);
    const bool   tail = (t == 127);              // pair 255 -> PE = 0

#pragma unroll
    for (int r = 0; r < ROWS_PER_GROUP; r++) {
        const float fi = (float)(base + r);
        float4 o;
        {
            float2 sc = pe_pair(fi, w.x);        // pair 2t (always < 255)
            o.x = e[r].x + sc.x;
            o.y = e[r].y + sc.y;
        }
        if (!tail) {
            float2 sc = pe_pair(fi, w.y);        // pair 2t+1
            o.z = e[r].z + sc.x;
            o.w = e[r].w + sc.y;
        } else {
            o.z = e[r].z;
            o.w = e[r].w;
        }
        // Streaming store: keep the 256MB output stream from evicting the
        // 103MB embedding table out of L2.
        __stcs(reinterpret_cast<float4*>(out) + ((size_t)(base + r) << 7) + t, o);
    }
}

extern "C" void kernel_launch(void* const* d_in, const int* in_sizes, int n_in,
                              void* d_out, int out_size) {
    const int*   tok = (const int*)d_in[0];     // token_ids, int32 [131072]
    const float* tab = (const float*)d_in[1];   // emb_table, fp32 [50257, 512]
    float*       out = (float*)d_out;           // fp32 [131072, 512]

    setup_freq_kernel<<<1, 256>>>();
    emb_pe_kernel<<<SEQ / (2 * ROWS_PER_GROUP), 256>>>(tok, tab, out);
}

// round 3
// speedup vs baseline: 1.3367x; 1.0214x over previous
#include <cuda_runtime.h>
#include <cuda_bf16.h>

// PositionalEmbedding: out[l, :] = emb_table[token_ids[l], :] + PE(l, :)
// PE pairs p in [0,255): col 2p = sin(l / 10000^(2p/512)), col 2p+1 = cos(...).
// Cols 510, 511 get PE = 0 (reference only fills 255 pairs).

#define SEQ   131072
#define DEPTH 512
#define ROWS_PER_GROUP 8   // rows handled by each 128-thread group

// Per-pair frequency w_p = 10000^(2p/512), correctly-rounded fp32 (computed in
// double so it matches the reference's fp32 frequency bit-for-bit).
__device__ float g_w[256];

__global__ void setup_freq_kernel() {
    int p = threadIdx.x;
    if (p < 255) {
        double y = (double)(2 * p) / 512.0;          // exact in double
        double w = exp(y * 9.210340371976184);       // ln(10000)
        g_w[p] = (float)w;
    } else if (p == 255) {
        g_w[p] = 1.0f;  // unused (guarded)
    }
}

// Accurate sin/cos of the fp32-rounded angle a = fl32(fi / w), mimicking
// jnp.sin/jnp.cos applied to the reference's fp32 angle.
//  - __fdiv_rn: IEEE round-to-nearest division (matches reference's angle bits)
//  - two-word Cody-Waite reduction mod 2pi (k <= 20861 for a <= 131071)
//  - MUFU sin/cos on the reduced argument |r| <= pi + 0.01
__device__ __forceinline__ float2 pe_pair(float fi, float w) {
    float a = __fdiv_rn(fi, w);
    float k = rintf(a * 0.15915494309189535f);
    // 2pi = HI + MID; HI = fl32(2pi), MID = 2pi - HI = -1.7484555e-7
    float r = fmaf(k, -6.283185307179586f, a);   // literal rounds to HI
    r = fmaf(k, 1.7484556e-07f, r);              // add back k*(HI - 2pi)
    float s, c;
    __sincosf(r, &s, &c);
    return make_float2(s, c);
}

__global__ void __launch_bounds__(256) emb_pe_kernel(
    const int*   __restrict__ tok,
    const float* __restrict__ tab,
    float*       __restrict__ out)
{
    const int tid  = threadIdx.x;
    const int t    = tid & 127;                  // float4 index within a row
    const int grp  = tid >> 7;                   // 0 or 1
    const int base = (blockIdx.x * 2 + grp) * ROWS_PER_GROUP;

    // ---- 8 token ids via two coalesced int4 loads (base is 8-aligned) ----
    const int4 tka = __ldg(reinterpret_cast<const int4*>(tok + base));
    const int4 tkb = __ldg(reinterpret_cast<const int4*>(tok + base + 4));
    const int tk[ROWS_PER_GROUP] = {tka.x, tka.y, tka.z, tka.w,
                                    tkb.x, tkb.y, tkb.z, tkb.w};

    // ---- front-batched independent table gathers (2KB-aligned rows) ----
    float4 e[ROWS_PER_GROUP];
#pragma unroll
    for (int r = 0; r < ROWS_PER_GROUP; r++)
        e[r] = __ldg(reinterpret_cast<const float4*>(tab) + ((size_t)tk[r] << 7) + t);

    // frequencies for pairs p0 = 2t, p1 = 2t+1 — coalesced float2 load
    const float2 w    = __ldg(reinterpret_cast<const float2*>(g_w) + t);
    const bool   tail = (t == 127);              // pair 255 -> PE = 0

#pragma unroll
    for (int r = 0; r < ROWS_PER_GROUP; r++) {
        const float fi = (float)(base + r);
        float4 o;
        {
            float2 sc = pe_pair(fi, w.x);        // pair 2t (always < 255)
            o.x = e[r].x + sc.x;
            o.y = e[r].y + sc.y;
        }
        if (!tail) {
            float2 sc = pe_pair(fi, w.y);        // pair 2t+1
            o.z = e[r].z + sc.x;
            o.w = e[r].w + sc.y;
        } else {
            o.z = e[r].z;
            o.w = e[r].w;
        }
        // Streaming store: keep the 256MB output stream from evicting the
        // 103MB embedding table out of L2.
        __stcs(reinterpret_cast<float4*>(out) + ((size_t)(base + r) << 7) + t, o);
    }
}

extern "C" void kernel_launch(void* const* d_in, const int* in_sizes, int n_in,
                              void* d_out, int out_size) {
    const int*   tok = (const int*)d_in[0];     // token_ids, int32 [131072]
    const float* tab = (const float*)d_in[1];   // emb_table, fp32 [50257, 512]
    float*       out = (float*)d_out;           // fp32 [131072, 512]

    setup_freq_kernel<<<1, 256>>>();
    emb_pe_kernel<<<SEQ / (2 * ROWS_PER_GROUP), 256>>>(tok, tab, out);
}